// round 1
// baseline (speedup 1.0000x reference)
#include <cuda_runtime.h>
#include <math.h>

#define H 128
#define W 128
#define HW (H*W)
#define NF 64          // feature channels
#define TT 5           // frames
#define BB 2           // batch

// ---------------- scratch (device globals; no runtime allocation) ----------------
__device__ float g_feats[BB*TT*NF*HW];       // [b][t][c][y][x]  (41.9 MB)
__device__ float g_half[BB*6*27*HW];         // [b][s][oc][y][x] s=0: f0*W[:, :64]; s=1..5: f_{s-1}*W[:,64:]
__device__ float g_wt[9*64*64];              // dcn weights transposed: [k][c][o]

// ---------------- kernel W-prep: transpose dcn_w (O,C,3,3) -> [k][c][o] ----------------
__global__ void wprep_kernel(const float* __restrict__ dcn_w) {
    int i = blockIdx.x * blockDim.x + threadIdx.x;
    if (i >= 9*64*64) return;
    int o = i & 63;
    int c = (i >> 6) & 63;
    int k = i >> 12;
    g_wt[i] = dcn_w[(o*64 + c)*9 + k];
}

// ---------------- kernel A: 3->64 conv3x3 SAME + bias + PReLU ----------------
// grid (64 tiles, 10 frames), block 256 (16x16 pixels), 64 accumulators/thread
__global__ void __launch_bounds__(256) init_conv_kernel(
    const float* __restrict__ x, const float* __restrict__ wgt,
    const float* __restrict__ bias, const float* __restrict__ prelu_a)
{
    __shared__ float sx[3][18][18];
    __shared__ float sw[27*64];   // [(ic*9+tap)*64 + oc]
    __shared__ float sb[64];
    int tid = threadIdx.x;
    int n = blockIdx.y;                 // 0..9  (b*5 + t)
    int ty0 = (blockIdx.x >> 3) * 16;
    int tx0 = (blockIdx.x & 7) * 16;

    // stage weights transposed
    for (int idx = tid; idx < 1728; idx += 256) {
        int oc = idx & 63;
        int r = idx >> 6;           // 0..26
        int ic = r / 9, tap = r % 9;
        sw[idx] = wgt[(oc*3 + ic)*9 + tap];
    }
    if (tid < 64) sb[tid] = bias[tid];

    // stage input tile with halo (zero pad)
    const float* xin = x + n*3*HW;
    for (int idx = tid; idx < 3*18*18; idx += 256) {
        int c = idx / 324;
        int r = (idx / 18) % 18;
        int col = idx % 18;
        int gy = ty0 + r - 1, gx = tx0 + col - 1;
        float v = 0.f;
        if (gy >= 0 && gy < H && gx >= 0 && gx < W) v = xin[c*HW + gy*W + gx];
        sx[c][r][col] = v;
    }
    __syncthreads();

    int ly = tid >> 4, lx = tid & 15;
    float acc[64];
    #pragma unroll
    for (int oc = 0; oc < 64; oc++) acc[oc] = sb[oc];

    for (int ic = 0; ic < 3; ic++) {
        for (int tap = 0; tap < 9; tap++) {
            int dy = tap / 3, dx = tap % 3;
            float v = sx[ic][ly + dy][lx + dx];
            const float* wp = &sw[(ic*9 + tap)*64];
            #pragma unroll
            for (int oc = 0; oc < 64; oc++) acc[oc] = fmaf(v, wp[oc], acc[oc]);
        }
    }
    float a = prelu_a[0];
    float* dst = g_feats + (size_t)n*NF*HW + (ty0 + ly)*W + (tx0 + lx);
    #pragma unroll
    for (int oc = 0; oc < 64; oc++) {
        float h = acc[oc];
        dst[oc*HW] = (h > 0.f) ? h : a*h;
    }
}

// ---------------- kernel B: half offset-conv, 64->27, SAME, no bias ----------------
// 12 tasks: task = b*6 + s.  s=0: input feats[b][0], weights offm_w[:, 0:64]
//                            s>=1: input feats[b][s-1], weights offm_w[:, 64:128]
// grid (32 tiles, 12 tasks), block 256; tile 16 rows x 32 cols; 2 px/thread; 27 acc each
__global__ void __launch_bounds__(256) half_conv_kernel(const float* __restrict__ offm_w)
{
    __shared__ float st[4][18][34];
    __shared__ float ws[4*9*27];   // [(c*9+tap)*27 + oc]
    int tid = threadIdx.x;
    int task = blockIdx.y;
    int b = task / 6, s = task % 6;
    int tsel = (s == 0) ? 0 : (s - 1);
    int icg0 = (s == 0) ? 0 : 64;
    int y0 = (blockIdx.x >> 2) * 16;
    int x0 = (blockIdx.x & 3) * 32;

    const float* src = g_feats + (size_t)((b*TT + tsel)*NF)*HW;
    int tx = tid & 15, ty = tid >> 4;

    float a0[27], a1[27];
    #pragma unroll
    for (int oc = 0; oc < 27; oc++) { a0[oc] = 0.f; a1[oc] = 0.f; }

    for (int icb = 0; icb < 64; icb += 4) {
        __syncthreads();
        // load input chunk tile with halo
        for (int idx = tid; idx < 4*18*34; idx += 256) {
            int c = idx / (18*34);
            int r = (idx / 34) % 18;
            int col = idx % 34;
            int gy = y0 + r - 1, gx = x0 + col - 1;
            float v = 0.f;
            if (gy >= 0 && gy < H && gx >= 0 && gx < W) v = src[(icb + c)*HW + gy*W + gx];
            st[c][r][col] = v;
        }
        // load weights chunk transposed
        for (int idx = tid; idx < 4*9*27; idx += 256) {
            int oc = idx % 27;
            int r = idx / 27;
            int tap = r % 9, c = r / 9;
            ws[idx] = offm_w[(oc*128 + icg0 + icb + c)*9 + tap];
        }
        __syncthreads();

        for (int c = 0; c < 4; c++) {
            for (int tap = 0; tap < 9; tap++) {
                int dy = tap / 3, dx = tap % 3;
                float v0 = st[c][ty + dy][tx + dx];
                float v1 = st[c][ty + dy][tx + 16 + dx];
                const float* wp = &ws[(c*9 + tap)*27];
                #pragma unroll
                for (int oc = 0; oc < 27; oc++) {
                    float wv = wp[oc];
                    a0[oc] = fmaf(v0, wv, a0[oc]);
                    a1[oc] = fmaf(v1, wv, a1[oc]);
                }
            }
        }
    }
    float* dst = g_half + (size_t)(task*27)*HW + (y0 + ty)*W + x0;
    #pragma unroll
    for (int oc = 0; oc < 27; oc++) {
        dst[oc*HW + tx] = a0[oc];
        dst[oc*HW + tx + 16] = a1[oc];
    }
}

// ---------------- kernel C: deformable sampling + 64x576 contraction ----------------
// grid (256 row-tiles of 64 px, 10 = j*2+b), block 256
__global__ void __launch_bounds__(256) dcn_kernel(
    const float* __restrict__ offm_b, const float* __restrict__ dcn_b,
    float* __restrict__ out)
{
    __shared__ __align__(16) float S[64*64];    // [c][px]
    __shared__ __align__(16) float Wt[64*64];   // [c][o]
    __shared__ int   sA[4][64];
    __shared__ float sWm[4][64];

    int tid = threadIdx.x;
    int jb = blockIdx.y;            // j*2 + b
    int j = jb >> 1, b = jb & 1;
    int y = blockIdx.x >> 1;
    int x0 = (blockIdx.x & 1) * 64;

    const float* fb = g_feats + (size_t)((b*TT + j)*NF)*HW;
    const float* h0 = g_half + (size_t)((b*6 + 0)*27)*HW;
    const float* h1 = g_half + (size_t)((b*6 + 1 + j)*27)*HW;

    int tx = tid & 15, ty = tid >> 4;
    int cg = tid >> 6, pxl6 = tid & 63;

    float acc[4][4];
    #pragma unroll
    for (int i = 0; i < 4; i++)
        #pragma unroll
        for (int jj = 0; jj < 4; jj++) acc[i][jj] = 0.f;

    for (int k = 0; k < 9; k++) {
        __syncthreads();   // protect S/Wt from previous tap's GEMM reads

        // stage transposed weights for this tap (coalesced)
        for (int i = tid; i < 4096; i += 256) Wt[i] = g_wt[k*4096 + i];

        // per-pixel bilinear meta (validity folded into mask-premultiplied weights)
        if (tid < 64) {
            int gx = x0 + tid;
            int pix = y*W + gx;
            float oy = h0[(k)*HW + pix] + h1[(k)*HW + pix] + offm_b[k];
            float ox = h0[(9+k)*HW + pix] + h1[(9+k)*HW + pix] + offm_b[9+k];
            float mm = h0[(18+k)*HW + pix] + h1[(18+k)*HW + pix] + offm_b[18+k];
            float mask = 1.f / (1.f + expf(-mm));
            float py = (float)(y + (k/3) - 1) + oy;
            float pxf = (float)(gx + (k%3) - 1) + ox;
            float y0f = floorf(py), x0f = floorf(pxf);
            float lyf = py - y0f, lxf = pxf - x0f;
            int yi = (int)y0f, xi = (int)x0f;
            bool vy0 = (yi >= 0) & (yi < H);
            bool vy1 = (yi >= -1) & (yi < H-1);
            bool vx0 = (xi >= 0) & (xi < W);
            bool vx1 = (xi >= -1) & (xi < W-1);
            int yc0 = min(max(yi, 0), H-1);
            int yc1 = min(max(yi+1, 0), H-1);
            int xc0 = min(max(xi, 0), W-1);
            int xc1 = min(max(xi+1, 0), W-1);
            float wy0 = 1.f - lyf, wy1 = lyf, wx0 = 1.f - lxf, wx1 = lxf;
            sA[0][tid] = yc0*W + xc0;  sWm[0][tid] = (vy0 && vx0) ? wy0*wx0*mask : 0.f;
            sA[1][tid] = yc0*W + xc1;  sWm[1][tid] = (vy0 && vx1) ? wy0*wx1*mask : 0.f;
            sA[2][tid] = yc1*W + xc0;  sWm[2][tid] = (vy1 && vx0) ? wy1*wx0*mask : 0.f;
            sA[3][tid] = yc1*W + xc1;  sWm[3][tid] = (vy1 && vx1) ? wy1*wx1*mask : 0.f;
        }
        __syncthreads();

        // gather 64ch x 64px sample tile
        {
            int a0 = sA[0][pxl6], a1 = sA[1][pxl6], a2 = sA[2][pxl6], a3 = sA[3][pxl6];
            float w0 = sWm[0][pxl6], w1 = sWm[1][pxl6], w2 = sWm[2][pxl6], w3 = sWm[3][pxl6];
            #pragma unroll
            for (int ci = 0; ci < 16; ci++) {
                int c = cg*16 + ci;
                const float* p = fb + c*HW;
                float sval = w0*p[a0] + w1*p[a1] + w2*p[a2] + w3*p[a3];
                S[c*64 + pxl6] = sval;
            }
        }
        __syncthreads();

        // 64x64x64 GEMM accumulate: acc[o 4][px 4]
        {
            const float4* S4 = (const float4*)S;
            const float4* W4 = (const float4*)Wt;
            #pragma unroll 8
            for (int kk = 0; kk < 64; kk++) {
                float4 av = W4[kk*16 + ty];
                float4 bv = S4[kk*16 + tx];
                acc[0][0] = fmaf(av.x, bv.x, acc[0][0]);
                acc[0][1] = fmaf(av.x, bv.y, acc[0][1]);
                acc[0][2] = fmaf(av.x, bv.z, acc[0][2]);
                acc[0][3] = fmaf(av.x, bv.w, acc[0][3]);
                acc[1][0] = fmaf(av.y, bv.x, acc[1][0]);
                acc[1][1] = fmaf(av.y, bv.y, acc[1][1]);
                acc[1][2] = fmaf(av.y, bv.z, acc[1][2]);
                acc[1][3] = fmaf(av.y, bv.w, acc[1][3]);
                acc[2][0] = fmaf(av.z, bv.x, acc[2][0]);
                acc[2][1] = fmaf(av.z, bv.y, acc[2][1]);
                acc[2][2] = fmaf(av.z, bv.z, acc[2][2]);
                acc[2][3] = fmaf(av.z, bv.w, acc[2][3]);
                acc[3][0] = fmaf(av.w, bv.x, acc[3][0]);
                acc[3][1] = fmaf(av.w, bv.y, acc[3][1]);
                acc[3][2] = fmaf(av.w, bv.z, acc[3][2]);
                acc[3][3] = fmaf(av.w, bv.w, acc[3][3]);
            }
        }
    }

    // epilogue: + bias, write output (T, B, 64, H, W)
    float* ob = out + (size_t)(jb*NF)*HW + y*W + x0;
    #pragma unroll
    for (int i = 0; i < 4; i++) {
        int o = ty*4 + i;
        float bi = __ldg(&dcn_b[o]);
        float4 r;
        r.x = acc[i][0] + bi;
        r.y = acc[i][1] + bi;
        r.z = acc[i][2] + bi;
        r.w = acc[i][3] + bi;
        *(float4*)(ob + o*HW + tx*4) = r;
    }
}

// ---------------- launch ----------------
extern "C" void kernel_launch(void* const* d_in, const int* in_sizes, int n_in,
                              void* d_out, int out_size) {
    const float* x       = (const float*)d_in[0];
    const float* init_w  = (const float*)d_in[1];
    const float* init_b  = (const float*)d_in[2];
    const float* prelu_a = (const float*)d_in[3];
    const float* offm_w  = (const float*)d_in[4];
    const float* offm_b  = (const float*)d_in[5];
    const float* dcn_w   = (const float*)d_in[6];
    const float* dcn_b   = (const float*)d_in[7];
    float* out = (float*)d_out;

    wprep_kernel<<<(9*64*64 + 255)/256, 256>>>(dcn_w);
    init_conv_kernel<<<dim3(64, 10), 256>>>(x, init_w, init_b, prelu_a);
    half_conv_kernel<<<dim3(32, 12), 256>>>(offm_w);
    dcn_kernel<<<dim3(256, 10), 256>>>(offm_b, dcn_b, out);
}

// round 2
// speedup vs baseline: 1.1528x; 1.1528x over previous
#include <cuda_runtime.h>
#include <math.h>

#define H 128
#define W 128
#define HW (H*W)
#define NF 64
#define TT 5
#define BB 2

// ---------------- scratch ----------------
__device__ float g_feats[BB*TT*NF*HW];       // NCHW  [b][t][c][y][x]
__device__ float g_fnhwc[BB*TT*HW*NF];       // NHWC  [b][t][y][x][c]
__device__ float g_half[BB*6*27*HW];         // [b][s][oc][y][x]
__device__ float g_wt[9*64*64];              // [k][c][o]

// ---------------- f32x2 helpers ----------------
typedef unsigned long long ull;
__device__ __forceinline__ ull pk2(float lo, float hi) {
    ull r; asm("mov.b64 %0, {%1,%2};" : "=l"(r) : "f"(lo), "f"(hi)); return r;
}
__device__ __forceinline__ void ffma2(ull& d, ull a, ull b) {
    asm("fma.rn.f32x2 %0, %1, %2, %0;" : "+l"(d) : "l"(a), "l"(b));
}
__device__ __forceinline__ float2 upk2(ull v) {
    float2 f; asm("mov.b64 {%0,%1}, %2;" : "=f"(f.x), "=f"(f.y) : "l"(v)); return f;
}

// ---------------- W-prep ----------------
__global__ void wprep_kernel(const float* __restrict__ dcn_w) {
    int i = blockIdx.x * blockDim.x + threadIdx.x;
    if (i >= 9*64*64) return;
    int o = i & 63;
    int c = (i >> 6) & 63;
    int k = i >> 12;
    g_wt[i] = dcn_w[(o*64 + c)*9 + k];
}

// ---------------- kernel A: 3->64 conv3x3 + bias + PReLU, writes NCHW + NHWC ----------------
__global__ void __launch_bounds__(256) init_conv_kernel(
    const float* __restrict__ x, const float* __restrict__ wgt,
    const float* __restrict__ bias, const float* __restrict__ prelu_a)
{
    __shared__ float sx[3][18][18];
    __shared__ __align__(8) float sw[27*64];
    __shared__ __align__(8) float sb[64];
    int tid = threadIdx.x;
    int n = blockIdx.y;
    int ty0 = (blockIdx.x >> 3) * 16;
    int tx0 = (blockIdx.x & 7) * 16;

    for (int idx = tid; idx < 1728; idx += 256) {
        int oc = idx & 63;
        int r = idx >> 6;
        int ic = r / 9, tap = r % 9;
        sw[idx] = wgt[(oc*3 + ic)*9 + tap];
    }
    if (tid < 64) sb[tid] = bias[tid];

    const float* xin = x + n*3*HW;
    for (int idx = tid; idx < 3*18*18; idx += 256) {
        int c = idx / 324;
        int r = (idx / 18) % 18;
        int col = idx % 18;
        int gy = ty0 + r - 1, gx = tx0 + col - 1;
        float v = 0.f;
        if (gy >= 0 && gy < H && gx >= 0 && gx < W) v = xin[c*HW + gy*W + gx];
        sx[c][r][col] = v;
    }
    __syncthreads();

    int ly = tid >> 4, lx = tid & 15;
    ull acc2[32];
    #pragma unroll
    for (int o2 = 0; o2 < 32; o2++) acc2[o2] = *(const ull*)&sb[2*o2];

    for (int ic = 0; ic < 3; ic++) {
        #pragma unroll
        for (int tap = 0; tap < 9; tap++) {
            int dy = tap / 3, dx = tap % 3;
            float v = sx[ic][ly + dy][lx + dx];
            ull v2 = pk2(v, v);
            const ull* wp = (const ull*)&sw[(ic*9 + tap)*64];
            #pragma unroll
            for (int o2 = 0; o2 < 32; o2++) ffma2(acc2[o2], v2, wp[o2]);
        }
    }
    float a = prelu_a[0];
    int pix = (ty0 + ly)*W + (tx0 + lx);
    float* dst = g_feats + (size_t)n*NF*HW + pix;
    float* nd  = g_fnhwc + ((size_t)n*HW + pix)*64;
    #pragma unroll
    for (int o2 = 0; o2 < 32; o2++) {
        float2 f = upk2(acc2[o2]);
        float h0 = (f.x > 0.f) ? f.x : a*f.x;
        float h1 = (f.y > 0.f) ? f.y : a*f.y;
        dst[(2*o2)*HW] = h0;
        dst[(2*o2+1)*HW] = h1;
        float2 w2; w2.x = h0; w2.y = h1;
        *(float2*)(nd + 2*o2) = w2;
    }
}

// ---------------- kernel B: half offset-conv 64->27 (padded 28), f32x2 over oc ----------------
__global__ void __launch_bounds__(256) half_conv_kernel(const float* __restrict__ offm_w)
{
    __shared__ float st[4][18][34];
    __shared__ __align__(8) float ws[4*9*28];
    int tid = threadIdx.x;
    int task = blockIdx.y;
    int b = task / 6, s = task % 6;
    int tsel = (s == 0) ? 0 : (s - 1);
    int icg0 = (s == 0) ? 0 : 64;
    int y0 = (blockIdx.x >> 2) * 16;
    int x0 = (blockIdx.x & 3) * 32;

    const float* src = g_feats + (size_t)((b*TT + tsel)*NF)*HW;
    int tx = tid & 15, ty = tid >> 4;

    ull a0[14], a1[14];
    #pragma unroll
    for (int o2 = 0; o2 < 14; o2++) { a0[o2] = 0ULL; a1[o2] = 0ULL; }

    for (int icb = 0; icb < 64; icb += 4) {
        __syncthreads();
        for (int idx = tid; idx < 4*18*34; idx += 256) {
            int c = idx / (18*34);
            int r = (idx / 34) % 18;
            int col = idx % 34;
            int gy = y0 + r - 1, gx = x0 + col - 1;
            float v = 0.f;
            if (gy >= 0 && gy < H && gx >= 0 && gx < W) v = src[(icb + c)*HW + gy*W + gx];
            st[c][r][col] = v;
        }
        for (int idx = tid; idx < 4*9*28; idx += 256) {
            int oc = idx % 28;
            int r = idx / 28;
            int tap = r % 9, c = r / 9;
            ws[idx] = (oc < 27) ? offm_w[(oc*128 + icg0 + icb + c)*9 + tap] : 0.f;
        }
        __syncthreads();

        #pragma unroll
        for (int c = 0; c < 4; c++) {
            #pragma unroll
            for (int tap = 0; tap < 9; tap++) {
                int dy = tap / 3, dx = tap % 3;
                float v0 = st[c][ty + dy][tx + dx];
                float v1 = st[c][ty + dy][tx + 16 + dx];
                ull v02 = pk2(v0, v0);
                ull v12 = pk2(v1, v1);
                const ull* wp = (const ull*)&ws[(c*9 + tap)*28];
                #pragma unroll
                for (int o2 = 0; o2 < 14; o2++) {
                    ull w2 = wp[o2];
                    ffma2(a0[o2], v02, w2);
                    ffma2(a1[o2], v12, w2);
                }
            }
        }
    }
    float* dst = g_half + (size_t)(task*27)*HW + (y0 + ty)*W + x0;
    #pragma unroll
    for (int o2 = 0; o2 < 14; o2++) {
        float2 f0 = upk2(a0[o2]);
        float2 f1 = upk2(a1[o2]);
        int oc = 2*o2;
        dst[oc*HW + tx] = f0.x;
        dst[oc*HW + tx + 16] = f1.x;
        if (oc + 1 < 27) {
            dst[(oc+1)*HW + tx] = f0.y;
            dst[(oc+1)*HW + tx + 16] = f1.y;
        }
    }
}

// ---------------- kernel C: deformable sampling + contraction, 64oc x 256px tile ----------------
// dynamic smem: S[64*256] | Wt[64*64] | sA[4*256] | sWm[4*256]  = 90112 B
__global__ void __launch_bounds__(256, 2) dcn_kernel(
    const float* __restrict__ offm_b, const float* __restrict__ dcn_b,
    float* __restrict__ out)
{
    extern __shared__ __align__(16) float smem[];
    float* S   = smem;                    // [c][256] with xor-swizzled 8-px blocks
    float* Wt  = smem + 64*256;           // [c][o]
    int*   sAi = (int*)(smem + 64*256 + 64*64);   // [4][256]
    float* sWm = (float*)(sAi + 4*256);           // [4][256]

    int tid = threadIdx.x;
    int jb = blockIdx.y;
    int j = jb >> 1, b = jb & 1;
    int y0 = blockIdx.x * 2;              // 2 rows per block

    const float* fb = g_fnhwc + (size_t)((b*TT + j))*HW*64;
    const float* h0 = g_half + (size_t)((b*6 + 0)*27)*HW;
    const float* h1 = g_half + (size_t)((b*6 + 1 + j)*27)*HW;

    int tx = tid & 31;                    // px block (8 px each)
    int ty = tid >> 5;                    // oc block (8 oc each)

    ull acc2[8][4];
    #pragma unroll
    for (int o = 0; o < 8; o++)
        #pragma unroll
        for (int p = 0; p < 4; p++) acc2[o][p] = 0ULL;

    for (int k = 0; k < 9; k++) {
        __syncthreads();    // previous GEMM done with S/Wt; previous gather done with sA/sWm

        // stage Wt for this tap
        for (int i = tid; i < 4096; i += 256) Wt[i] = g_wt[k*4096 + i];

        // per-pixel meta (256 px)
        {
            int px = tid;
            int gx = px & 127;
            int yy = y0 + (px >> 7);
            int pix = yy*W + gx;
            float oy = h0[k*HW + pix] + h1[k*HW + pix] + offm_b[k];
            float ox = h0[(9+k)*HW + pix] + h1[(9+k)*HW + pix] + offm_b[9+k];
            float mm = h0[(18+k)*HW + pix] + h1[(18+k)*HW + pix] + offm_b[18+k];
            float mask = 1.f / (1.f + expf(-mm));
            float py  = (float)(yy + (k/3) - 1) + oy;
            float pxf = (float)(gx + (k%3) - 1) + ox;
            float y0f = floorf(py), x0f = floorf(pxf);
            float lyf = py - y0f, lxf = pxf - x0f;
            int yi = (int)y0f, xi = (int)x0f;
            bool vy0 = (yi >= 0) & (yi < H);
            bool vy1 = (yi >= -1) & (yi < H-1);
            bool vx0 = (xi >= 0) & (xi < W);
            bool vx1 = (xi >= -1) & (xi < W-1);
            int yc0 = min(max(yi, 0), H-1);
            int yc1 = min(max(yi+1, 0), H-1);
            int xc0 = min(max(xi, 0), W-1);
            int xc1 = min(max(xi+1, 0), W-1);
            float wy0 = 1.f - lyf, wy1 = lyf, wx0 = 1.f - lxf, wx1 = lxf;
            sAi[0*256 + px] = (yc0*W + xc0) * 64;  sWm[0*256 + px] = (vy0 && vx0) ? wy0*wx0*mask : 0.f;
            sAi[1*256 + px] = (yc0*W + xc1) * 64;  sWm[1*256 + px] = (vy0 && vx1) ? wy0*wx1*mask : 0.f;
            sAi[2*256 + px] = (yc1*W + xc0) * 64;  sWm[2*256 + px] = (vy1 && vx0) ? wy1*wx0*mask : 0.f;
            sAi[3*256 + px] = (yc1*W + xc1) * 64;  sWm[3*256 + px] = (vy1 && vx1) ? wy1*wx1*mask : 0.f;
        }
        __syncthreads();

        // gather: 1024 (px, quarter) tasks, NHWC coalesced float4 loads
        #pragma unroll
        for (int it = 0; it < 4; it++) {
            int task = tid + it*256;
            int px = task >> 2;
            int q = task & 3;
            int a0 = sAi[0*256 + px], a1 = sAi[1*256 + px];
            int a2 = sAi[2*256 + px], a3 = sAi[3*256 + px];
            float w0 = sWm[0*256 + px], w1 = sWm[1*256 + px];
            float w2 = sWm[2*256 + px], w3 = sWm[3*256 + px];
            int blk = px >> 3, pof = px & 7;
            #pragma unroll
            for (int i = 0; i < 4; i++) {
                int ch4 = i*4 + q;            // float4 group index (0..15)
                float4 v0 = *(const float4*)(fb + a0 + ch4*4);
                float4 v1 = *(const float4*)(fb + a1 + ch4*4);
                float4 v2 = *(const float4*)(fb + a2 + ch4*4);
                float4 v3 = *(const float4*)(fb + a3 + ch4*4);
                float4 r;
                r.x = fmaf(w3, v3.x, fmaf(w2, v2.x, fmaf(w1, v1.x, w0*v0.x)));
                r.y = fmaf(w3, v3.y, fmaf(w2, v2.y, fmaf(w1, v1.y, w0*v0.y)));
                r.z = fmaf(w3, v3.z, fmaf(w2, v2.z, fmaf(w1, v1.z, w0*v0.z)));
                r.w = fmaf(w3, v3.w, fmaf(w2, v2.w, fmaf(w1, v1.w, w0*v0.w)));
                int xb = ((blk ^ (ch4 & 3)) << 3) + pof;   // xor key = (c>>2)&3
                int c0 = ch4*4;
                S[(c0+0)*256 + xb] = r.x;
                S[(c0+1)*256 + xb] = r.y;
                S[(c0+2)*256 + xb] = r.z;
                S[(c0+3)*256 + xb] = r.w;
            }
        }
        __syncthreads();

        // GEMM accumulate: acc[8 oc][8 px] via f32x2
        #pragma unroll 4
        for (int kk = 0; kk < 64; kk++) {
            float4 wA0 = *(const float4*)&Wt[kk*64 + ty*8];
            float4 wA1 = *(const float4*)&Wt[kk*64 + ty*8 + 4];
            int xb = (tx ^ ((kk >> 2) & 3)) << 3;
            const ull* bp = (const ull*)&S[kk*256 + xb];
            ull b0 = bp[0], b1 = bp[1], b2 = bp[2], b3 = bp[3];
            ull sv;
            sv = pk2(wA0.x, wA0.x); ffma2(acc2[0][0], sv, b0); ffma2(acc2[0][1], sv, b1); ffma2(acc2[0][2], sv, b2); ffma2(acc2[0][3], sv, b3);
            sv = pk2(wA0.y, wA0.y); ffma2(acc2[1][0], sv, b0); ffma2(acc2[1][1], sv, b1); ffma2(acc2[1][2], sv, b2); ffma2(acc2[1][3], sv, b3);
            sv = pk2(wA0.z, wA0.z); ffma2(acc2[2][0], sv, b0); ffma2(acc2[2][1], sv, b1); ffma2(acc2[2][2], sv, b2); ffma2(acc2[2][3], sv, b3);
            sv = pk2(wA0.w, wA0.w); ffma2(acc2[3][0], sv, b0); ffma2(acc2[3][1], sv, b1); ffma2(acc2[3][2], sv, b2); ffma2(acc2[3][3], sv, b3);
            sv = pk2(wA1.x, wA1.x); ffma2(acc2[4][0], sv, b0); ffma2(acc2[4][1], sv, b1); ffma2(acc2[4][2], sv, b2); ffma2(acc2[4][3], sv, b3);
            sv = pk2(wA1.y, wA1.y); ffma2(acc2[5][0], sv, b0); ffma2(acc2[5][1], sv, b1); ffma2(acc2[5][2], sv, b2); ffma2(acc2[5][3], sv, b3);
            sv = pk2(wA1.z, wA1.z); ffma2(acc2[6][0], sv, b0); ffma2(acc2[6][1], sv, b1); ffma2(acc2[6][2], sv, b2); ffma2(acc2[6][3], sv, b3);
            sv = pk2(wA1.w, wA1.w); ffma2(acc2[7][0], sv, b0); ffma2(acc2[7][1], sv, b1); ffma2(acc2[7][2], sv, b2); ffma2(acc2[7][3], sv, b3);
        }
    }

    // epilogue
    int pxb = tx * 8;
    int yy = y0 + (pxb >> 7);
    int xx = pxb & 127;
    float* ob = out + (size_t)jb*64*HW + yy*W + xx;
    #pragma unroll
    for (int o = 0; o < 8; o++) {
        int oc = ty*8 + o;
        float bi = __ldg(&dcn_b[oc]);
        float2 f0 = upk2(acc2[o][0]);
        float2 f1 = upk2(acc2[o][1]);
        float2 f2 = upk2(acc2[o][2]);
        float2 f3 = upk2(acc2[o][3]);
        float4 lo, hi;
        lo.x = f0.x + bi; lo.y = f0.y + bi; lo.z = f1.x + bi; lo.w = f1.y + bi;
        hi.x = f2.x + bi; hi.y = f2.y + bi; hi.z = f3.x + bi; hi.w = f3.y + bi;
        *(float4*)(ob + (size_t)oc*HW) = lo;
        *(float4*)(ob + (size_t)oc*HW + 4) = hi;
    }
}

// ---------------- launch ----------------
extern "C" void kernel_launch(void* const* d_in, const int* in_sizes, int n_in,
                              void* d_out, int out_size) {
    const float* x       = (const float*)d_in[0];
    const float* init_w  = (const float*)d_in[1];
    const float* init_b  = (const float*)d_in[2];
    const float* prelu_a = (const float*)d_in[3];
    const float* offm_w  = (const float*)d_in[4];
    const float* offm_b  = (const float*)d_in[5];
    const float* dcn_w   = (const float*)d_in[6];
    const float* dcn_b   = (const float*)d_in[7];
    float* out = (float*)d_out;

    static bool attr_set = false;
    if (!attr_set) {
        cudaFuncSetAttribute(dcn_kernel, cudaFuncAttributeMaxDynamicSharedMemorySize, 90112);
        attr_set = true;
    }

    wprep_kernel<<<(9*64*64 + 255)/256, 256>>>(dcn_w);
    init_conv_kernel<<<dim3(64, 10), 256>>>(x, init_w, init_b, prelu_a);
    half_conv_kernel<<<dim3(32, 12), 256>>>(offm_w);
    dcn_kernel<<<dim3(64, 10), 256, 90112>>>(offm_b, dcn_b, out);
}

// round 5
// speedup vs baseline: 1.2855x; 1.1151x over previous
#include <cuda_runtime.h>
#include <math.h>

#define H 128
#define W 128
#define HW (H*W)
#define NF 64
#define TT 5
#define BB 2

// ---------------- scratch ----------------
__device__ float g_feats[BB*TT*NF*HW];       // NCHW
__device__ float g_fnhwc[BB*TT*HW*NF];       // NHWC
__device__ float g_half[BB*6*27*HW];
__device__ float g_wt[9*64*64];              // [k][c][o]

// ---------------- f32x2 helpers ----------------
typedef unsigned long long ull;
__device__ __forceinline__ ull pk2(float lo, float hi) {
    ull r; asm("mov.b64 %0, {%1,%2};" : "=l"(r) : "f"(lo), "f"(hi)); return r;
}
__device__ __forceinline__ void ffma2(ull& d, ull a, ull b) {
    asm("fma.rn.f32x2 %0, %1, %2, %0;" : "+l"(d) : "l"(a), "l"(b));
}
__device__ __forceinline__ float2 upk2(ull v) {
    float2 f; asm("mov.b64 {%0,%1}, %2;" : "=f"(f.x), "=f"(f.y) : "l"(v)); return f;
}

// ---------------- W-prep: MUST cover all 36864 elements ----------------
__global__ void wprep_kernel(const float* __restrict__ dcn_w) {
    int i = blockIdx.x * blockDim.x + threadIdx.x;
    if (i >= 9*64*64) return;
    int o = i & 63;
    int c = (i >> 6) & 63;
    int k = i >> 12;
    g_wt[i] = dcn_w[(o*64 + c)*9 + k];
}

// ---------------- kernel A: 3->64 conv3x3 + bias + PReLU -> NCHW only ----------------
__global__ void __launch_bounds__(256) init_conv_kernel(
    const float* __restrict__ x, const float* __restrict__ wgt,
    const float* __restrict__ bias, const float* __restrict__ prelu_a)
{
    __shared__ float sx[3][18][18];
    __shared__ __align__(8) float sw[27*64];
    __shared__ __align__(8) float sb[64];
    int tid = threadIdx.x;
    int n = blockIdx.y;
    int ty0 = (blockIdx.x >> 3) * 16;
    int tx0 = (blockIdx.x & 7) * 16;

    for (int idx = tid; idx < 1728; idx += 256) {
        int oc = idx & 63;
        int r = idx >> 6;
        int ic = r / 9, tap = r % 9;
        sw[idx] = wgt[(oc*3 + ic)*9 + tap];
    }
    if (tid < 64) sb[tid] = bias[tid];

    const float* xin = x + n*3*HW;
    for (int idx = tid; idx < 3*18*18; idx += 256) {
        int c = idx / 324;
        int r = (idx / 18) % 18;
        int col = idx % 18;
        int gy = ty0 + r - 1, gx = tx0 + col - 1;
        float v = 0.f;
        if (gy >= 0 && gy < H && gx >= 0 && gx < W) v = xin[c*HW + gy*W + gx];
        sx[c][r][col] = v;
    }
    __syncthreads();

    int ly = tid >> 4, lx = tid & 15;
    ull acc2[32];
    #pragma unroll
    for (int o2 = 0; o2 < 32; o2++) acc2[o2] = *(const ull*)&sb[2*o2];

    for (int ic = 0; ic < 3; ic++) {
        #pragma unroll
        for (int tap = 0; tap < 9; tap++) {
            int dy = tap / 3, dx = tap % 3;
            float v = sx[ic][ly + dy][lx + dx];
            ull v2 = pk2(v, v);
            const ull* wp = (const ull*)&sw[(ic*9 + tap)*64];
            #pragma unroll
            for (int o2 = 0; o2 < 32; o2++) ffma2(acc2[o2], v2, wp[o2]);
        }
    }
    float a = prelu_a[0];
    int pix = (ty0 + ly)*W + (tx0 + lx);
    float* dst = g_feats + (size_t)n*NF*HW + pix;
    #pragma unroll
    for (int o2 = 0; o2 < 32; o2++) {
        float2 f = upk2(acc2[o2]);
        dst[(2*o2)*HW]   = (f.x > 0.f) ? f.x : a*f.x;
        dst[(2*o2+1)*HW] = (f.y > 0.f) ? f.y : a*f.y;
    }
}

// ---------------- transpose NCHW -> NHWC (coalesced both sides) ----------------
__global__ void __launch_bounds__(256) transpose_kernel()
{
    __shared__ float tile[64][65];
    int tid = threadIdx.x;
    int n = blockIdx.y;
    int px0 = blockIdx.x * 64;
    const float* src = g_feats + (size_t)n*NF*HW + px0;
    float* dst = g_fnhwc + ((size_t)n*HW + px0)*64;

    #pragma unroll
    for (int i = 0; i < 16; i++) {
        int idx = tid + i*256;
        int c = idx >> 6, xx = idx & 63;
        tile[c][xx] = src[c*HW + xx];
    }
    __syncthreads();
    #pragma unroll
    for (int i = 0; i < 16; i++) {
        int idx = tid + i*256;
        int p = idx >> 6, c = idx & 63;
        dst[p*64 + c] = tile[c][p];
    }
}

// ---------------- kernel B: half offset-conv 64->27(pad 28), 16x16 tile, 128 thr ----------------
__global__ void __launch_bounds__(128) half_conv_kernel(const float* __restrict__ offm_w)
{
    __shared__ float st[4][18][19];
    __shared__ __align__(8) float ws[4*9*28];
    int tid = threadIdx.x;
    int task = blockIdx.y;
    int b = task / 6, s = task % 6;
    int tsel = (s == 0) ? 0 : (s - 1);
    int icg0 = (s == 0) ? 0 : 64;
    int y0 = (blockIdx.x >> 3) * 16;
    int x0 = (blockIdx.x & 7) * 16;

    const float* src = g_feats + (size_t)((b*TT + tsel)*NF)*HW;
    int tx = tid & 7, ty = tid >> 3;

    ull a0[14], a1[14];
    #pragma unroll
    for (int o2 = 0; o2 < 14; o2++) { a0[o2] = 0ULL; a1[o2] = 0ULL; }

    for (int icb = 0; icb < 64; icb += 4) {
        __syncthreads();
        for (int idx = tid; idx < 4*18*18; idx += 128) {
            int c = idx / 324;
            int r = (idx / 18) % 18;
            int col = idx % 18;
            int gy = y0 + r - 1, gx = x0 + col - 1;
            float v = 0.f;
            if (gy >= 0 && gy < H && gx >= 0 && gx < W) v = src[(icb + c)*HW + gy*W + gx];
            st[c][r][col] = v;
        }
        for (int idx = tid; idx < 4*9*28; idx += 128) {
            int oc = idx % 28;
            int r = idx / 28;
            int tap = r % 9, c = r / 9;
            ws[idx] = (oc < 27) ? offm_w[(oc*128 + icg0 + icb + c)*9 + tap] : 0.f;
        }
        __syncthreads();

        #pragma unroll
        for (int c = 0; c < 4; c++) {
            #pragma unroll
            for (int tap = 0; tap < 9; tap++) {
                int dy = tap / 3, dx = tap % 3;
                float v0 = st[c][ty + dy][tx + dx];
                float v1 = st[c][ty + dy][tx + 8 + dx];
                ull v02 = pk2(v0, v0);
                ull v12 = pk2(v1, v1);
                const ull* wp = (const ull*)&ws[(c*9 + tap)*28];
                #pragma unroll
                for (int o2 = 0; o2 < 14; o2++) {
                    ull w2 = wp[o2];
                    ffma2(a0[o2], v02, w2);
                    ffma2(a1[o2], v12, w2);
                }
            }
        }
    }
    float* dst = g_half + (size_t)(task*27)*HW + (y0 + ty)*W + x0;
    #pragma unroll
    for (int o2 = 0; o2 < 14; o2++) {
        float2 f0 = upk2(a0[o2]);
        float2 f1 = upk2(a1[o2]);
        int oc = 2*o2;
        dst[oc*HW + tx] = f0.x;
        dst[oc*HW + tx + 8] = f1.x;
        if (oc + 1 < 27) {
            dst[(oc+1)*HW + tx] = f0.y;
            dst[(oc+1)*HW + tx + 8] = f1.y;
        }
    }
}

// ---------------- kernel C: dcn, 64oc x 128px tile, 128 threads, 4 blocks/SM ----------------
// smem: S[64*128] 32KB | Wt[64*64] 16KB | sAi[4*128] | sWm[4*128]  = 53248 B
__global__ void __launch_bounds__(128, 4) dcn_kernel(
    const float* __restrict__ offm_b, const float* __restrict__ dcn_b,
    float* __restrict__ out)
{
    extern __shared__ __align__(16) float smem[];
    float* S   = smem;                                 // [c][128], 8-px blocks xor-swizzled
    float* Wt  = smem + 64*128;                        // [c][o]
    int*   sAi = (int*)(smem + 64*128 + 64*64);        // [4][128]
    float* sWm = (float*)(sAi + 4*128);                // [4][128]

    int tid = threadIdx.x;
    int jb = blockIdx.y;
    int j = jb >> 1, b = jb & 1;
    int y = blockIdx.x;                                // one row of 128 px

    const float* fb = g_fnhwc + (size_t)(b*TT + j)*HW*64;
    const float* h0 = g_half + (size_t)((b*6 + 0)*27)*HW;
    const float* h1 = g_half + (size_t)((b*6 + 1 + j)*27)*HW;

    int tx = tid & 15;                                 // px block (8 px)
    int ty = tid >> 4;                                 // oc block (8 oc)

    ull acc2[8][4];
    #pragma unroll
    for (int o = 0; o < 8; o++)
        #pragma unroll
        for (int p = 0; p < 4; p++) acc2[o][p] = 0ULL;

    for (int k = 0; k < 9; k++) {
        __syncthreads();   // prev GEMM done with S/Wt; prev gather done with sAi/sWm

        #pragma unroll
        for (int i = 0; i < 32; i++) Wt[tid + i*128] = g_wt[k*4096 + tid + i*128];

        // per-pixel meta (one px per thread)
        {
            int gx = tid;
            int pix = y*W + gx;
            float oy = h0[k*HW + pix] + h1[k*HW + pix] + offm_b[k];
            float ox = h0[(9+k)*HW + pix] + h1[(9+k)*HW + pix] + offm_b[9+k];
            float mm = h0[(18+k)*HW + pix] + h1[(18+k)*HW + pix] + offm_b[18+k];
            float mask = 1.f / (1.f + expf(-mm));
            float py  = (float)(y + (k/3) - 1) + oy;
            float pxf = (float)(gx + (k%3) - 1) + ox;
            float y0f = floorf(py), x0f = floorf(pxf);
            float lyf = py - y0f, lxf = pxf - x0f;
            int yi = (int)y0f, xi = (int)x0f;
            bool vy0 = (yi >= 0) & (yi < H);
            bool vy1 = (yi >= -1) & (yi < H-1);
            bool vx0 = (xi >= 0) & (xi < W);
            bool vx1 = (xi >= -1) & (xi < W-1);
            int yc0 = min(max(yi, 0), H-1);
            int yc1 = min(max(yi+1, 0), H-1);
            int xc0 = min(max(xi, 0), W-1);
            int xc1 = min(max(xi+1, 0), W-1);
            float wy0 = 1.f - lyf, wy1 = lyf, wx0 = 1.f - lxf, wx1 = lxf;
            sAi[0*128 + tid] = (yc0*W + xc0) * 64;  sWm[0*128 + tid] = (vy0 && vx0) ? wy0*wx0*mask : 0.f;
            sAi[1*128 + tid] = (yc0*W + xc1) * 64;  sWm[1*128 + tid] = (vy0 && vx1) ? wy0*wx1*mask : 0.f;
            sAi[2*128 + tid] = (yc1*W + xc0) * 64;  sWm[2*128 + tid] = (vy1 && vx0) ? wy1*wx0*mask : 0.f;
            sAi[3*128 + tid] = (yc1*W + xc1) * 64;  sWm[3*128 + tid] = (vy1 && vx1) ? wy1*wx1*mask : 0.f;
        }
        __syncthreads();

        // gather: 1024 tasks = 128 px * 8 channel-lanes, 128B contiguous per 8-lane group
        #pragma unroll
        for (int it = 0; it < 8; it++) {
            int task = tid + it*128;
            int px = task >> 3;
            int q = task & 7;
            int a0 = sAi[0*128 + px], a1 = sAi[1*128 + px];
            int a2 = sAi[2*128 + px], a3 = sAi[3*128 + px];
            float w0 = sWm[0*128 + px], w1 = sWm[1*128 + px];
            float w2 = sWm[2*128 + px], w3 = sWm[3*128 + px];
            int blk = px >> 3, pof = px & 7;
            #pragma unroll
            for (int i = 0; i < 2; i++) {
                int ch4 = q + i*8;                 // 0..15
                float4 v0 = *(const float4*)(fb + a0 + ch4*4);
                float4 v1 = *(const float4*)(fb + a1 + ch4*4);
                float4 v2 = *(const float4*)(fb + a2 + ch4*4);
                float4 v3 = *(const float4*)(fb + a3 + ch4*4);
                float4 r;
                r.x = fmaf(w3, v3.x, fmaf(w2, v2.x, fmaf(w1, v1.x, w0*v0.x)));
                r.y = fmaf(w3, v3.y, fmaf(w2, v2.y, fmaf(w1, v1.y, w0*v0.y)));
                r.z = fmaf(w3, v3.z, fmaf(w2, v2.z, fmaf(w1, v1.z, w0*v0.z)));
                r.w = fmaf(w3, v3.w, fmaf(w2, v2.w, fmaf(w1, v1.w, w0*v0.w)));
                int xb = ((blk ^ (ch4 & 3)) << 3) + pof;
                int c0 = ch4*4;
                S[(c0+0)*128 + xb] = r.x;
                S[(c0+1)*128 + xb] = r.y;
                S[(c0+2)*128 + xb] = r.z;
                S[(c0+3)*128 + xb] = r.w;
            }
        }
        __syncthreads();

        // GEMM accumulate: acc[8 oc][8 px] via f32x2
        #pragma unroll 4
        for (int kk = 0; kk < 64; kk++) {
            float4 wA0 = *(const float4*)&Wt[kk*64 + ty*8];
            float4 wA1 = *(const float4*)&Wt[kk*64 + ty*8 + 4];
            int xb = (tx ^ ((kk >> 2) & 3)) << 3;
            const ull* bp = (const ull*)&S[kk*128 + xb];
            ull b0 = bp[0], b1 = bp[1], b2 = bp[2], b3 = bp[3];
            ull sv;
            sv = pk2(wA0.x, wA0.x); ffma2(acc2[0][0], sv, b0); ffma2(acc2[0][1], sv, b1); ffma2(acc2[0][2], sv, b2); ffma2(acc2[0][3], sv, b3);
            sv = pk2(wA0.y, wA0.y); ffma2(acc2[1][0], sv, b0); ffma2(acc2[1][1], sv, b1); ffma2(acc2[1][2], sv, b2); ffma2(acc2[1][3], sv, b3);
            sv = pk2(wA0.z, wA0.z); ffma2(acc2[2][0], sv, b0); ffma2(acc2[2][1], sv, b1); ffma2(acc2[2][2], sv, b2); ffma2(acc2[2][3], sv, b3);
            sv = pk2(wA0.w, wA0.w); ffma2(acc2[3][0], sv, b0); ffma2(acc2[3][1], sv, b1); ffma2(acc2[3][2], sv, b2); ffma2(acc2[3][3], sv, b3);
            sv = pk2(wA1.x, wA1.x); ffma2(acc2[4][0], sv, b0); ffma2(acc2[4][1], sv, b1); ffma2(acc2[4][2], sv, b2); ffma2(acc2[4][3], sv, b3);
            sv = pk2(wA1.y, wA1.y); ffma2(acc2[5][0], sv, b0); ffma2(acc2[5][1], sv, b1); ffma2(acc2[5][2], sv, b2); ffma2(acc2[5][3], sv, b3);
            sv = pk2(wA1.z, wA1.z); ffma2(acc2[6][0], sv, b0); ffma2(acc2[6][1], sv, b1); ffma2(acc2[6][2], sv, b2); ffma2(acc2[6][3], sv, b3);
            sv = pk2(wA1.w, wA1.w); ffma2(acc2[7][0], sv, b0); ffma2(acc2[7][1], sv, b1); ffma2(acc2[7][2], sv, b2); ffma2(acc2[7][3], sv, b3);
        }
    }

    // epilogue
    float* ob = out + (size_t)jb*64*HW + y*W + tx*8;
    #pragma unroll
    for (int o = 0; o < 8; o++) {
        int oc = ty*8 + o;
        float bi = __ldg(&dcn_b[oc]);
        float2 f0 = upk2(acc2[o][0]);
        float2 f1 = upk2(acc2[o][1]);
        float2 f2 = upk2(acc2[o][2]);
        float2 f3 = upk2(acc2[o][3]);
        float4 lo, hi;
        lo.x = f0.x + bi; lo.y = f0.y + bi; lo.z = f1.x + bi; lo.w = f1.y + bi;
        hi.x = f2.x + bi; hi.y = f2.y + bi; hi.z = f3.x + bi; hi.w = f3.y + bi;
        *(float4*)(ob + (size_t)oc*HW) = lo;
        *(float4*)(ob + (size_t)oc*HW + 4) = hi;
    }
}

// ---------------- launch ----------------
extern "C" void kernel_launch(void* const* d_in, const int* in_sizes, int n_in,
                              void* d_out, int out_size) {
    const float* x       = (const float*)d_in[0];
    const float* init_w  = (const float*)d_in[1];
    const float* init_b  = (const float*)d_in[2];
    const float* prelu_a = (const float*)d_in[3];
    const float* offm_w  = (const float*)d_in[4];
    const float* offm_b  = (const float*)d_in[5];
    const float* dcn_w   = (const float*)d_in[6];
    const float* dcn_b   = (const float*)d_in[7];
    float* out = (float*)d_out;

    static bool attr_set = false;
    if (!attr_set) {
        cudaFuncSetAttribute(dcn_kernel, cudaFuncAttributeMaxDynamicSharedMemorySize, 53248);
        attr_set = true;
    }

    wprep_kernel<<<(9*64*64 + 255)/256, 256>>>(dcn_w);   // 144 blocks — covers all 36864
    init_conv_kernel<<<dim3(64, 10), 256>>>(x, init_w, init_b, prelu_a);
    transpose_kernel<<<dim3(256, 10), 256>>>();
    half_conv_kernel<<<dim3(64, 12), 128>>>(offm_w);
    dcn_kernel<<<dim3(128, 10), 128, 53248>>>(offm_b, dcn_b, out);
}